// round 16
// baseline (speedup 1.0000x reference)
#include <cuda_runtime.h>
#include <cuda_bf16.h>
#include <cuda_fp16.h>
#include <cstdint>

#define NN   100000
#define MPAD 100096          // 782 * 128
#define EEM  3200000
#define NF   512
#define NH   256
#define NCLS 64
#define KHOP 10
#define SCAN_B 1024
#define NBLK_SCAN ((NN + SCAN_B - 1) / SCAN_B)

// ---------------- scratch ----------------
__device__ int   g_cnt[NN];
__device__ int   g_off[NN + 1];
__device__ int   g_cur[NN];
__device__ int   g_bsum[128];
__device__ int2  g_sw[EEM];                          // packed (src, weight-bits)
__device__ float g_dis[NN];
__device__ float g_selfw[NN];
__device__ __nv_bfloat16 g_xh[(size_t)MPAD * NF];    // x hi/lo (pad rows zero)
__device__ __nv_bfloat16 g_xl[(size_t)MPAD * NF];
__device__ __nv_bfloat16 g_w1th[(size_t)NH * NF];    // W1^T hi  [n, k]
__device__ __nv_bfloat16 g_w1tl[(size_t)NH * NF];
__device__ __nv_bfloat16 g_w2th[(size_t)NCLS * NH];
__device__ __nv_bfloat16 g_w2tl[(size_t)NCLS * NH];
__device__ __nv_bfloat16 g_h1h[(size_t)MPAD * NH];   // relu(h1) hi/lo (pad rows zero)
__device__ __nv_bfloat16 g_h1l[(size_t)MPAD * NH];
__device__ __half g_hA[(size_t)NN * NCLS];           // prop state fp16 (accum fp32)
__device__ __half g_hB[(size_t)NN * NCLS];
__device__ float  g_hid[(size_t)NN * NCLS];

// ---------------- helpers ----------------
__device__ __forceinline__ uint32_t smem_u32(const void* p) {
    uint32_t a;
    asm("{ .reg .u64 t; cvta.to.shared.u64 t, %1; cvt.u32.u64 %0, t; }" : "=r"(a) : "l"(p));
    return a;
}
#define SWZ128(o) ((o) ^ (((o) >> 3) & 0x70))

__device__ __forceinline__ void ldsm_x4(uint32_t addr, uint32_t r[4]) {
    asm volatile("ldmatrix.sync.aligned.m8n8.x4.shared.b16 {%0,%1,%2,%3}, [%4];"
                 : "=r"(r[0]), "=r"(r[1]), "=r"(r[2]), "=r"(r[3]) : "r"(addr));
}
__device__ __forceinline__ void mma_bf16(float d[4], const uint32_t a[4], const uint32_t b[2]) {
    asm volatile("mma.sync.aligned.m16n8k16.row.col.f32.bf16.bf16.f32 "
                 "{%0,%1,%2,%3}, {%4,%5,%6,%7}, {%8,%9}, {%0,%1,%2,%3};"
                 : "+f"(d[0]), "+f"(d[1]), "+f"(d[2]), "+f"(d[3])
                 : "r"(a[0]), "r"(a[1]), "r"(a[2]), "r"(a[3]), "r"(b[0]), "r"(b[1]));
}
__device__ __forceinline__ void cp16(uint32_t smem, const void* g) {
    asm volatile("cp.async.cg.shared.global [%0], [%1], 16;" :: "r"(smem), "l"(g));
}
#define CP_COMMIT() asm volatile("cp.async.commit_group;" ::: "memory")
#define CP_WAIT0()  asm volatile("cp.async.wait_group 0;" ::: "memory")
#define CP_WAIT1()  asm volatile("cp.async.wait_group 1;" ::: "memory")

__device__ __forceinline__ void split_pair(float a, float b, uint32_t& hi, uint32_t& lo) {
    __nv_bfloat16 h0 = __float2bfloat16_rn(a);
    __nv_bfloat16 h1 = __float2bfloat16_rn(b);
    __nv_bfloat16 l0 = __float2bfloat16_rn(a - __bfloat162float(h0));
    __nv_bfloat16 l1 = __float2bfloat16_rn(b - __bfloat162float(h1));
    __nv_bfloat162 H; H.x = h0; H.y = h1;
    __nv_bfloat162 L; L.x = l0; L.y = l1;
    hi = *(uint32_t*)&H; lo = *(uint32_t*)&L;
}

// ---------------- pre-split kernels ----------------
__global__ void k_split_w(const float* __restrict__ W, __nv_bfloat16* __restrict__ Th,
                          __nv_bfloat16* __restrict__ Tl, int K, int Nc) {
    int i = blockIdx.x * blockDim.x + threadIdx.x;
    if (i < K * Nc) {
        int k = i / Nc, n = i % Nc;
        float v = W[i];
        __nv_bfloat16 h = __float2bfloat16_rn(v);
        Th[(size_t)n * K + k] = h;
        Tl[(size_t)n * K + k] = __float2bfloat16_rn(v - __bfloat162float(h));
    }
}

// x [N, NF] fp32 -> xh/xl [MPAD, NF] bf16 (pad rows zero)
__global__ void k_split_x(const float* __restrict__ X, __nv_bfloat16* __restrict__ Xh,
                          __nv_bfloat16* __restrict__ Xl, int M) {
    size_t i4 = (size_t)blockIdx.x * blockDim.x + threadIdx.x;   // float4 index
    if (i4 >= (size_t)MPAD * NF / 4) return;
    int row = (int)(i4 / (NF / 4));
    float4 v = (row < M) ? *((const float4*)X + i4) : make_float4(0.f, 0.f, 0.f, 0.f);
    uint2 hi, lo;
    split_pair(v.x, v.y, hi.x, lo.x);
    split_pair(v.z, v.w, hi.y, lo.y);
    *((uint2*)Xh + i4) = hi;
    *((uint2*)Xl + i4) = lo;
}

// ================= GEMM1: h1(bf16 hi/lo) = relu(x @ W1 + b1) =================
// BM=128, BN=128, KC=64, 512 threads, 16 warps (4M x 4N), warp tile 32x32.
// Pure cp.async double-buffered pipeline (A pre-split to bf16 hi/lo).
__global__ __launch_bounds__(512) void k_gemm1(
    const __nv_bfloat16* __restrict__ Ah, const __nv_bfloat16* __restrict__ Al,
    const __nv_bfloat16* __restrict__ BTh, const __nv_bfloat16* __restrict__ BTl,
    const float* __restrict__ bias,
    __nv_bfloat16* __restrict__ O1h, __nv_bfloat16* __restrict__ O1l, int M)
{
    constexpr int KT = NF, NT = 128;
    constexpr int NCH = KT / 64;                     // 8
    constexpr int OFF_AH = 0, OFF_AL = 16384, OFF_BH = 32768, OFF_BL = 49152;
    constexpr int STG = 65536;                       // 64KB / stage

    extern __shared__ char smem_raw[];
    uint32_t sb0 = smem_u32(smem_raw);
    uint32_t pad = (1024u - (sb0 & 1023u)) & 1023u;
    uint32_t sb = sb0 + pad;

    int tid = threadIdx.x, wid = tid >> 5, lane = tid & 31;
    int brow = blockIdx.y * 128, bcol = blockIdx.x * NT;   // x = N tile (A sharers adjacent)
    int wm = (wid & 3) * 32, wn = (wid >> 2) * 32;

    // A loader: am = row 0..127, asub (0..3) -> 2 of 8 16B groups
    int am = tid >> 2, asub = tid & 3;
    // B loader: bn = row 0..127, bsub (0..3) -> 2 of 8 16B groups
    int bn = tid & (NT - 1), bsub = tid >> 7;

    auto issue = [&](int c, int buf) {
        uint32_t base = sb + buf * STG;
        const __nv_bfloat16* pah = Ah + (size_t)(brow + am) * KT + c * 64;
        const __nv_bfloat16* pal = Al + (size_t)(brow + am) * KT + c * 64;
#pragma unroll
        for (int i = 0; i < 2; i++) {
            int g = asub * 2 + i;
            uint32_t sw = SWZ128((uint32_t)(am * 128 + g * 16));
            cp16(base + OFF_AH + sw, pah + g * 8);
            cp16(base + OFF_AL + sw, pal + g * 8);
        }
        const __nv_bfloat16* pbh = BTh + (size_t)(bcol + bn) * KT + c * 64;
        const __nv_bfloat16* pbl = BTl + (size_t)(bcol + bn) * KT + c * 64;
#pragma unroll
        for (int i = 0; i < 2; i++) {
            int g = bsub * 2 + i;
            uint32_t sw = SWZ128((uint32_t)(bn * 128 + g * 16));
            cp16(base + OFF_BH + sw, pbh + g * 8);
            cp16(base + OFF_BL + sw, pbl + g * 8);
        }
    };

    float acc[2][4][4];
#pragma unroll
    for (int mt = 0; mt < 2; mt++)
#pragma unroll
        for (int nt = 0; nt < 4; nt++)
#pragma unroll
            for (int j = 0; j < 4; j++) acc[mt][nt][j] = 0.0f;

    issue(0, 0); CP_COMMIT();
    issue(1, 1); CP_COMMIT();
    CP_WAIT1();
    __syncthreads();

    for (int c = 0; c < NCH; c++) {
        int buf = c & 1;
        uint32_t sbase = sb + buf * STG;
#pragma unroll
        for (int ks = 0; ks < 4; ks++) {
            uint32_t ahf[2][4], alf[2][4], bhf[2][4], blf[2][4];
#pragma unroll
            for (int mt = 0; mt < 2; mt++) {
                uint32_t bo = (uint32_t)((wm + mt * 16 + (lane & 15)) * 128
                                         + ks * 32 + (lane >> 4) * 16);
                uint32_t sw = SWZ128(bo);
                ldsm_x4(sbase + OFF_AH + sw, ahf[mt]);
                ldsm_x4(sbase + OFF_AL + sw, alf[mt]);
            }
#pragma unroll
            for (int np = 0; np < 2; np++) {
                uint32_t bo = (uint32_t)((wn + np * 16 + (lane & 7) + ((lane >> 4) & 1) * 8) * 128
                                         + ks * 32 + ((lane >> 3) & 1) * 16);
                uint32_t sw = SWZ128(bo);
                ldsm_x4(sbase + OFF_BH + sw, bhf[np]);
                ldsm_x4(sbase + OFF_BL + sw, blf[np]);
            }
            // combo-outer: 8 independent mma between same-acc reuse
#pragma unroll
            for (int combo = 0; combo < 3; combo++)
#pragma unroll
                for (int mt = 0; mt < 2; mt++)
#pragma unroll
                    for (int nt = 0; nt < 4; nt++) {
                        const uint32_t* ap = (combo == 2) ? alf[mt] : ahf[mt];
                        const uint32_t* bp = (combo == 1) ? &blf[nt >> 1][(nt & 1) * 2]
                                                          : &bhf[nt >> 1][(nt & 1) * 2];
                        mma_bf16(acc[mt][nt], ap, bp);
                    }
        }
        __syncthreads();
        if (c + 2 < NCH) { issue(c + 2, buf); CP_COMMIT(); CP_WAIT1(); __syncthreads(); }
        else if (c + 1 < NCH) { CP_WAIT0(); __syncthreads(); }
    }

    // ---- epilogue: relu + bf16 hi/lo split out ----
#pragma unroll
    for (int mt = 0; mt < 2; mt++) {
        int r0 = brow + wm + mt * 16 + (lane >> 2);
#pragma unroll
        for (int nt = 0; nt < 4; nt++) {
            int cc = bcol + wn + nt * 8 + (lane & 3) * 2;
            float b0 = bias[cc], b1 = bias[cc + 1];
#pragma unroll
            for (int half = 0; half < 2; half++) {
                int r = r0 + half * 8;
                if (r < M) {
                    float vx = fmaxf(acc[mt][nt][half * 2 + 0] + b0, 0.f);
                    float vy = fmaxf(acc[mt][nt][half * 2 + 1] + b1, 0.f);
                    uint32_t hi, lo;
                    split_pair(vx, vy, hi, lo);
                    *(uint32_t*)(O1h + (size_t)r * NH + cc) = hi;
                    *(uint32_t*)(O1l + (size_t)r * NH + cc) = lo;
                }
            }
        }
    }
}

// ================= GEMM2: hA(fp16) = h1 @ W2 + b2 ; hid = temp[0]*hA =================
__global__ __launch_bounds__(256, 2) void k_gemm2(
    const __nv_bfloat16* __restrict__ Ah, const __nv_bfloat16* __restrict__ Al,
    const __nv_bfloat16* __restrict__ BTh, const __nv_bfloat16* __restrict__ BTl,
    const float* __restrict__ bias, __half* __restrict__ O1, float* __restrict__ O2,
    const float* __restrict__ temp, int M)
{
    constexpr int KT = NH, NT = 64, WN = 32;
    constexpr int NCH = KT / 64;                     // 4
    constexpr int OFF_AH = 0, OFF_AL = 16384, OFF_BH = 32768, OFF_BL = 32768 + NT * 128;
    constexpr int STG = 2 * 16384 + 2 * NT * 128;    // 48KB / stage

    extern __shared__ char smem_raw[];
    uint32_t sb0 = smem_u32(smem_raw);
    uint32_t pad = (1024u - (sb0 & 1023u)) & 1023u;
    uint32_t sb = sb0 + pad;

    int tid = threadIdx.x, wid = tid >> 5, lane = tid & 31;
    int brow = blockIdx.x * 128;
    int wm = (wid & 3) * 32, wn = (wid >> 2) * WN;

    int am = tid >> 1, asub = tid & 1;
    int bn = tid & (NT - 1), bsub = tid >> 6;

    auto issue = [&](int c, int buf) {
        uint32_t base = sb + buf * STG;
        const __nv_bfloat16* pah = Ah + (size_t)(brow + am) * KT + c * 64;
        const __nv_bfloat16* pal = Al + (size_t)(brow + am) * KT + c * 64;
#pragma unroll
        for (int i = 0; i < 4; i++) {
            int g = asub * 4 + i;
            uint32_t sw = SWZ128((uint32_t)(am * 128 + g * 16));
            cp16(base + OFF_AH + sw, pah + g * 8);
            cp16(base + OFF_AL + sw, pal + g * 8);
        }
        const __nv_bfloat16* pbh = BTh + (size_t)bn * KT + c * 64;
        const __nv_bfloat16* pbl = BTl + (size_t)bn * KT + c * 64;
#pragma unroll
        for (int i = 0; i < 2; i++) {
            int g = bsub * 2 + i;
            uint32_t sw = SWZ128((uint32_t)(bn * 128 + g * 16));
            cp16(base + OFF_BH + sw, pbh + g * 8);
            cp16(base + OFF_BL + sw, pbl + g * 8);
        }
    };

    float acc[2][4][4];
#pragma unroll
    for (int mt = 0; mt < 2; mt++)
#pragma unroll
        for (int nt = 0; nt < 4; nt++)
#pragma unroll
            for (int j = 0; j < 4; j++) acc[mt][nt][j] = 0.0f;

    issue(0, 0); CP_COMMIT();
    issue(1, 1); CP_COMMIT();
    CP_WAIT1();
    __syncthreads();

    for (int c = 0; c < NCH; c++) {
        int buf = c & 1;
        uint32_t sbase = sb + buf * STG;
#pragma unroll
        for (int ks = 0; ks < 4; ks++) {
            uint32_t ahf[2][4], alf[2][4], bhf[2][4], blf[2][4];
#pragma unroll
            for (int mt = 0; mt < 2; mt++) {
                uint32_t bo = (uint32_t)((wm + mt * 16 + (lane & 15)) * 128
                                         + ks * 32 + (lane >> 4) * 16);
                uint32_t sw = SWZ128(bo);
                ldsm_x4(sbase + OFF_AH + sw, ahf[mt]);
                ldsm_x4(sbase + OFF_AL + sw, alf[mt]);
            }
#pragma unroll
            for (int np = 0; np < 2; np++) {
                uint32_t bo = (uint32_t)((wn + np * 16 + (lane & 7) + ((lane >> 4) & 1) * 8) * 128
                                         + ks * 32 + ((lane >> 3) & 1) * 16);
                uint32_t sw = SWZ128(bo);
                ldsm_x4(sbase + OFF_BH + sw, bhf[np]);
                ldsm_x4(sbase + OFF_BL + sw, blf[np]);
            }
#pragma unroll
            for (int combo = 0; combo < 3; combo++)
#pragma unroll
                for (int mt = 0; mt < 2; mt++)
#pragma unroll
                    for (int nt = 0; nt < 4; nt++) {
                        const uint32_t* ap = (combo == 2) ? alf[mt] : ahf[mt];
                        const uint32_t* bp = (combo == 1) ? &blf[nt >> 1][(nt & 1) * 2]
                                                          : &bhf[nt >> 1][(nt & 1) * 2];
                        mma_bf16(acc[mt][nt], ap, bp);
                    }
        }
        __syncthreads();
        if (c + 2 < NCH) { issue(c + 2, buf); CP_COMMIT(); CP_WAIT1(); __syncthreads(); }
        else if (c + 1 < NCH) { CP_WAIT0(); __syncthreads(); }
    }

    float t0 = __ldg(temp);
#pragma unroll
    for (int mt = 0; mt < 2; mt++) {
        int r0 = brow + wm + mt * 16 + (lane >> 2);
#pragma unroll
        for (int nt = 0; nt < 4; nt++) {
            int cc = wn + nt * 8 + (lane & 3) * 2;
            float b0 = bias[cc], b1 = bias[cc + 1];
#pragma unroll
            for (int half = 0; half < 2; half++) {
                int r = r0 + half * 8;
                if (r < M) {
                    float vx = acc[mt][nt][half * 2 + 0] + b0;
                    float vy = acc[mt][nt][half * 2 + 1] + b1;
                    *(__half2*)(O1 + (size_t)r * NCLS + cc) = __floats2half2_rn(vx, vy);
                    float2 s; s.x = t0 * vx; s.y = t0 * vy;
                    *(float2*)(O2 + (size_t)r * NCLS + cc) = s;
                }
            }
        }
    }
}

// ---------------- CSR build ----------------
__global__ void k_zero_cnt(int* cnt, int n) {
    int i = blockIdx.x * blockDim.x + threadIdx.x;
    if (i < n) cnt[i] = 0;
}
__global__ void k_hist(const int* __restrict__ colp, int* cnt, int E) {
    int e = blockIdx.x * blockDim.x + threadIdx.x;
    if (e < E) atomicAdd(&cnt[colp[e]], 1);
}
__global__ __launch_bounds__(SCAN_B) void k_scan_block(
    const int* __restrict__ cnt, int* __restrict__ off, int* __restrict__ bsum, int n)
{
    __shared__ int s[SCAN_B];
    int i = blockIdx.x * SCAN_B + threadIdx.x;
    int v = (i < n) ? cnt[i] : 0;
    s[threadIdx.x] = v;
    __syncthreads();
#pragma unroll
    for (int d = 1; d < SCAN_B; d <<= 1) {
        int t = (threadIdx.x >= d) ? s[threadIdx.x - d] : 0;
        __syncthreads();
        s[threadIdx.x] += t;
        __syncthreads();
    }
    if (i < n) off[i] = s[threadIdx.x] - v;
    if (threadIdx.x == SCAN_B - 1) bsum[blockIdx.x] = s[SCAN_B - 1];
}
__global__ void k_scan_bsum(int* bsum, int nb, int* off, int n, int E) {
    int acc = 0;
    for (int i = 0; i < nb; i++) { int v = bsum[i]; bsum[i] = acc; acc += v; }
    off[n] = E;
}
__global__ __launch_bounds__(SCAN_B) void k_add_off(
    int* off, const int* __restrict__ bsum, int* cur, int n)
{
    int i = blockIdx.x * SCAN_B + threadIdx.x;
    if (i < n) {
        int v = off[i] + bsum[blockIdx.x];
        off[i] = v;
        cur[i] = v;
    }
}
__global__ void k_node_norm(const int* __restrict__ cnt, float* dis, float* selfw, int n) {
    int i = blockIdx.x * blockDim.x + threadIdx.x;
    if (i < n) {
        float d = (float)(cnt[i] + 1);
        dis[i]   = rsqrtf(d);
        selfw[i] = 1.0f / d;
    }
}
__global__ void k_scatter(const int* __restrict__ row, const int* __restrict__ colp,
                          const float* __restrict__ dis, int* cur,
                          int2* __restrict__ sw, int E) {
    int e = blockIdx.x * blockDim.x + threadIdx.x;
    if (e < E) {
        int r = row[e], c = colp[e];
        int pos = atomicAdd(&cur[c], 1);
        sw[pos] = make_int2(r, __float_as_int(dis[r] * dis[c]));
    }
}

// ---------------- fused CSR propagation (fp16 state, fp32 accum, packed edges) ----------------
__global__ __launch_bounds__(256) void k_prop(
    const int* __restrict__ off, const int2* __restrict__ sw,
    const float* __restrict__ selfw, const __half2* __restrict__ hc, __half2* __restrict__ hn,
    float2* __restrict__ hid, const float* __restrict__ temp, int kidx, int N)
{
    int gw = (blockIdx.x * blockDim.x + threadIdx.x) >> 5;
    if (gw >= N) return;
    int lane = threadIdx.x & 31;

    int s = off[gw];
    int e = off[gw + 1];
    float accx = 0.0f, accy = 0.0f;

    for (int base = s; base < e; base += 32) {
        int m = e - base; if (m > 32) m = 32;
        int idx = 0; float wv = 0.0f;
        if (lane < m) {
            int2 p = sw[base + lane];
            idx = p.x;
            wv  = __int_as_float(p.y);
        }
#pragma unroll 4
        for (int t = 0; t < m; t++) {
            int   ib = __shfl_sync(0xFFFFFFFFu, idx, t);
            float wb = __shfl_sync(0xFFFFFFFFu, wv,  t);
            float2 v = __half22float2(hc[(size_t)ib * 32 + lane]);
            accx += wb * v.x;
            accy += wb * v.y;
        }
    }
    float swv = selfw[gw];
    float2 hv = __half22float2(hc[(size_t)gw * 32 + lane]);
    accx += swv * hv.x;
    accy += swv * hv.y;

    size_t o = (size_t)gw * 32 + lane;
    hn[o] = __floats2half2_rn(accx, accy);

    float tc = temp[kidx];
    float2 hd = hid[o];
    hd.x += tc * accx;
    hd.y += tc * accy;
    hid[o] = hd;
}

// ---------------- log_softmax ----------------
__global__ void k_logsoftmax(const float* __restrict__ H, float* __restrict__ out, int N) {
    int gw = (blockIdx.x * blockDim.x + threadIdx.x) >> 5;
    int lane = threadIdx.x & 31;
    if (gw >= N) return;
    const float* h = H + (size_t)gw * NCLS;
    float v0 = h[lane];
    float v1 = h[lane + 32];
    float m = fmaxf(v0, v1);
#pragma unroll
    for (int off = 16; off > 0; off >>= 1)
        m = fmaxf(m, __shfl_xor_sync(0xFFFFFFFFu, m, off));
    float sum = __expf(v0 - m) + __expf(v1 - m);
#pragma unroll
    for (int off = 16; off > 0; off >>= 1)
        sum += __shfl_xor_sync(0xFFFFFFFFu, sum, off);
    float lse = m + __logf(sum);
    float* o = out + (size_t)gw * NCLS;
    o[lane]      = v0 - lse;
    o[lane + 32] = v1 - lse;
}

// ---------------- launch ----------------
extern "C" void kernel_launch(void* const* d_in, const int* in_sizes, int n_in,
                              void* d_out, int out_size) {
    const float* x    = (const float*)d_in[0];
    const int*   ei   = (const int*)d_in[1];
    const float* W1   = (const float*)d_in[2];
    const float* b1   = (const float*)d_in[3];
    const float* W2   = (const float*)d_in[4];
    const float* b2   = (const float*)d_in[5];
    const float* temp = (const float*)d_in[6];

    int N = in_sizes[0] / NF;
    int E = in_sizes[1] / 2;
    const int* row  = ei;
    const int* colp = ei + E;

    int *cnt, *off, *cur, *bsum;
    int2 *sw;
    float *dis, *selfw, *hid;
    __half *hA, *hB;
    __nv_bfloat16 *xh, *xl, *w1th, *w1tl, *w2th, *w2tl, *h1h, *h1l;
    cudaGetSymbolAddress((void**)&cnt,   g_cnt);
    cudaGetSymbolAddress((void**)&off,   g_off);
    cudaGetSymbolAddress((void**)&cur,   g_cur);
    cudaGetSymbolAddress((void**)&bsum,  g_bsum);
    cudaGetSymbolAddress((void**)&sw,    g_sw);
    cudaGetSymbolAddress((void**)&dis,   g_dis);
    cudaGetSymbolAddress((void**)&selfw, g_selfw);
    cudaGetSymbolAddress((void**)&xh,    g_xh);
    cudaGetSymbolAddress((void**)&xl,    g_xl);
    cudaGetSymbolAddress((void**)&w1th,  g_w1th);
    cudaGetSymbolAddress((void**)&w1tl,  g_w1tl);
    cudaGetSymbolAddress((void**)&w2th,  g_w2th);
    cudaGetSymbolAddress((void**)&w2tl,  g_w2tl);
    cudaGetSymbolAddress((void**)&h1h,   g_h1h);
    cudaGetSymbolAddress((void**)&h1l,   g_h1l);
    cudaGetSymbolAddress((void**)&hA,    g_hA);
    cudaGetSymbolAddress((void**)&hB,    g_hB);
    cudaGetSymbolAddress((void**)&hid,   g_hid);

    const int T = 256;
    int nblk = (N + 127) / 128;                               // 782
    const int SM1 = 2 * 65536 + 1024;                         // 132096 (1 CTA/SM, 512 thr)
    const int SM2 = 2 * (2 * 16384 + 2 * 64 * 128) + 1024;    //  99328
    cudaFuncSetAttribute(k_gemm1, cudaFuncAttributeMaxDynamicSharedMemorySize, SM1);
    cudaFuncSetAttribute(k_gemm2, cudaFuncAttributeMaxDynamicSharedMemorySize, SM2);

    // launch order places k_gemm1 at slot 4 (ncu -s window)
    k_split_w  <<<(NF * NH + T - 1) / T, T>>>(W1, w1th, w1tl, NF, NH);     // 1
    k_split_w  <<<(NH * NCLS + T - 1) / T, T>>>(W2, w2th, w2tl, NH, NCLS); // 2
    long long nx4 = (long long)MPAD * NF / 4;
    k_split_x  <<<(int)((nx4 + T - 1) / T), T>>>(x, xh, xl, N);             // 3
    dim3 g1(NH / 128, nblk);                              // x = N-tiles (A sharers adjacent)
    k_gemm1    <<<g1, 512, SM1>>>(xh, xl, w1th, w1tl, b1, h1h, h1l, N);     // 4 <- profiled
    k_zero_cnt <<<(N + T - 1) / T, T>>>(cnt, N);                            // 5
    k_hist     <<<(E + T - 1) / T, T>>>(colp, cnt, E);
    k_scan_block<<<NBLK_SCAN, SCAN_B>>>(cnt, off, bsum, N);
    k_scan_bsum<<<1, 1>>>(bsum, NBLK_SCAN, off, N, E);
    k_add_off  <<<NBLK_SCAN, SCAN_B>>>(off, bsum, cur, N);
    k_node_norm<<<(N + T - 1) / T, T>>>(cnt, dis, selfw, N);
    k_scatter  <<<(E + T - 1) / T, T>>>(row, colp, dis, cur, sw, E);
    k_gemm2    <<<nblk, 256, SM2>>>(h1h, h1l, w2th, w2tl, b2, hA, hid, temp, N);

    __half* curh = hA;
    __half* nxth = hB;
    int pblocks = (int)(((long long)N * 32 + T - 1) / T);
    for (int k = 0; k < KHOP; k++) {
        k_prop<<<pblocks, T>>>(off, sw, selfw,
                               (const __half2*)curh, (__half2*)nxth,
                               (float2*)hid, temp, k + 1, N);
        __half* t2 = curh; curh = nxth; nxth = t2;
    }

    k_logsoftmax<<<(int)(((long long)N * 32 + T - 1) / T), T>>>(hid, (float*)d_out, N);
}

// round 17
// speedup vs baseline: 1.0800x; 1.0800x over previous
#include <cuda_runtime.h>
#include <cuda_bf16.h>
#include <cuda_fp16.h>
#include <cstdint>

#define NN   100000
#define MPAD 100096          // 782 * 128
#define EEM  3200000
#define NF   512
#define NH   256
#define NCLS 64
#define KHOP 10
#define SCAN_B 1024
#define NBLK_SCAN ((NN + SCAN_B - 1) / SCAN_B)

// ---------------- scratch ----------------
__device__ int   g_cnt[NN];
__device__ int   g_off[NN + 1];
__device__ int   g_cur[NN];
__device__ int   g_bsum[128];
__device__ int2  g_sw[EEM];                          // packed (src, weight-bits)
__device__ float g_dis[NN];
__device__ float g_selfw[NN];
__device__ __nv_bfloat16 g_w1th[(size_t)NH * NF];    // W1^T hi  [n, k]
__device__ __nv_bfloat16 g_w1tl[(size_t)NH * NF];
__device__ __nv_bfloat16 g_w2th[(size_t)NCLS * NH];
__device__ __nv_bfloat16 g_w2tl[(size_t)NCLS * NH];
__device__ __nv_bfloat16 g_h1h[(size_t)MPAD * NH];   // relu(h1) hi/lo (pad rows zero)
__device__ __nv_bfloat16 g_h1l[(size_t)MPAD * NH];
__device__ __half g_hA[(size_t)NN * NCLS];           // prop state fp16 (accum fp32)
__device__ __half g_hB[(size_t)NN * NCLS];
__device__ float  g_hid[(size_t)NN * NCLS];

// ---------------- helpers ----------------
__device__ __forceinline__ uint32_t smem_u32(const void* p) {
    uint32_t a;
    asm("{ .reg .u64 t; cvta.to.shared.u64 t, %1; cvt.u32.u64 %0, t; }" : "=r"(a) : "l"(p));
    return a;
}
#define SWZ128(o) ((o) ^ (((o) >> 3) & 0x70))

__device__ __forceinline__ void ldsm_x4(uint32_t addr, uint32_t r[4]) {
    asm volatile("ldmatrix.sync.aligned.m8n8.x4.shared.b16 {%0,%1,%2,%3}, [%4];"
                 : "=r"(r[0]), "=r"(r[1]), "=r"(r[2]), "=r"(r[3]) : "r"(addr));
}
__device__ __forceinline__ void mma_bf16(float d[4], const uint32_t a[4], const uint32_t b[2]) {
    asm volatile("mma.sync.aligned.m16n8k16.row.col.f32.bf16.bf16.f32 "
                 "{%0,%1,%2,%3}, {%4,%5,%6,%7}, {%8,%9}, {%0,%1,%2,%3};"
                 : "+f"(d[0]), "+f"(d[1]), "+f"(d[2]), "+f"(d[3])
                 : "r"(a[0]), "r"(a[1]), "r"(a[2]), "r"(a[3]), "r"(b[0]), "r"(b[1]));
}
__device__ __forceinline__ void cp16(uint32_t smem, const void* g) {
    asm volatile("cp.async.cg.shared.global [%0], [%1], 16;" :: "r"(smem), "l"(g));
}
#define CP_COMMIT() asm volatile("cp.async.commit_group;" ::: "memory")
#define CP_WAIT0()  asm volatile("cp.async.wait_group 0;" ::: "memory")
#define CP_WAIT1()  asm volatile("cp.async.wait_group 1;" ::: "memory")

__device__ __forceinline__ void split_pair(float a, float b, uint32_t& hi, uint32_t& lo) {
    __nv_bfloat16 h0 = __float2bfloat16_rn(a);
    __nv_bfloat16 h1 = __float2bfloat16_rn(b);
    __nv_bfloat16 l0 = __float2bfloat16_rn(a - __bfloat162float(h0));
    __nv_bfloat16 l1 = __float2bfloat16_rn(b - __bfloat162float(h1));
    __nv_bfloat162 H; H.x = h0; H.y = h1;
    __nv_bfloat162 L; L.x = l0; L.y = l1;
    hi = *(uint32_t*)&H; lo = *(uint32_t*)&L;
}

// ---------------- weight pre-split (transpose, fp32 -> bf16 hi/lo) ----------------
__global__ void k_split_w(const float* __restrict__ W, __nv_bfloat16* __restrict__ Th,
                          __nv_bfloat16* __restrict__ Tl, int K, int Nc) {
    int i = blockIdx.x * blockDim.x + threadIdx.x;
    if (i < K * Nc) {
        int k = i / Nc, n = i % Nc;
        float v = W[i];
        __nv_bfloat16 h = __float2bfloat16_rn(v);
        Th[(size_t)n * K + k] = h;
        Tl[(size_t)n * K + k] = __float2bfloat16_rn(v - __bfloat162float(h));
    }
}

// ================= GEMM1: h1(bf16 hi/lo) = relu(x @ W1 + b1) =================
// BM=128, BN=128, KC=64, 512 threads, 16 warps (4M x 4N), warp tile 32x32.
// In-kernel fp32->bf16 hi/lo A conversion (register-staged), double-buffered.
__global__ __launch_bounds__(512) void k_gemm1(
    const float* __restrict__ A, const __nv_bfloat16* __restrict__ BTh,
    const __nv_bfloat16* __restrict__ BTl, const float* __restrict__ bias,
    __nv_bfloat16* __restrict__ O1h, __nv_bfloat16* __restrict__ O1l, int M)
{
    constexpr int KT = NF, NT = 128;
    constexpr int NCH = KT / 64;                     // 8
    constexpr int OFF_AH = 0, OFF_AL = 16384, OFF_BH = 32768, OFF_BL = 49152;
    constexpr int STG = 65536;                       // 64KB / stage

    extern __shared__ char smem_raw[];
    uint32_t sb0 = smem_u32(smem_raw);
    uint32_t pad = (1024u - (sb0 & 1023u)) & 1023u;
    char* sm = smem_raw + pad;
    uint32_t sb = sb0 + pad;

    int tid = threadIdx.x, wid = tid >> 5, lane = tid & 31;
    int brow = blockIdx.y * 128, bcol = blockIdx.x * NT;   // x = N tile (A sharers adjacent)
    int wm = (wid & 3) * 32, wn = (wid >> 2) * 32;

    // A loader (warp-contiguous): each warp covers 8 rows; per i, 2 full rows (512B)
    int arow_base = wid * 8 + (lane >> 4);     // +i*2
    int af4 = lane & 15;
    // B loader: bn = output-col row; bsub selects 2 of 8 16B groups
    int bn = tid & (NT - 1), bsub = tid >> 7;

    float4 areg[4];
    auto a_load = [&](int c) {
#pragma unroll
        for (int i = 0; i < 4; i++) {
            int r = arow_base + i * 2;
            int gm = brow + r;
            areg[i] = (gm < M) ? *(const float4*)(A + (size_t)gm * KT + c * 64 + af4 * 4)
                               : make_float4(0.f, 0.f, 0.f, 0.f);
        }
    };
    auto a_store = [&](int buf) {
        char* dst = sm + buf * STG;
#pragma unroll
        for (int i = 0; i < 4; i++) {
            int r = arow_base + i * 2;
            uint2 hi, lo;
            split_pair(areg[i].x, areg[i].y, hi.x, lo.x);
            split_pair(areg[i].z, areg[i].w, hi.y, lo.y);
            uint32_t sw = SWZ128((uint32_t)(r * 128 + af4 * 8));
            *(uint2*)(dst + OFF_AH + sw) = hi;
            *(uint2*)(dst + OFF_AL + sw) = lo;
        }
    };
    auto b_issue = [&](int c, int buf) {
        const __nv_bfloat16* bh = BTh + (size_t)(bcol + bn) * KT + c * 64;
        const __nv_bfloat16* bl = BTl + (size_t)(bcol + bn) * KT + c * 64;
        uint32_t base = sb + buf * STG;
#pragma unroll
        for (int i = 0; i < 2; i++) {
            int g = bsub * 2 + i;
            uint32_t sw = SWZ128((uint32_t)(bn * 128 + g * 16));
            cp16(base + OFF_BH + sw, bh + g * 8);
            cp16(base + OFF_BL + sw, bl + g * 8);
        }
    };

    float acc[2][4][4];
#pragma unroll
    for (int mt = 0; mt < 2; mt++)
#pragma unroll
        for (int nt = 0; nt < 4; nt++)
#pragma unroll
            for (int j = 0; j < 4; j++) acc[mt][nt][j] = 0.0f;

    a_load(0); a_store(0); b_issue(0, 0); CP_COMMIT();
    a_load(1); b_issue(1, 1); CP_COMMIT();
    CP_WAIT1();
    __syncthreads();

    for (int c = 0; c < NCH; c++) {
        int buf = c & 1;
        uint32_t sbase = sb + buf * STG;
#pragma unroll
        for (int ks = 0; ks < 4; ks++) {
            uint32_t ahf[2][4], alf[2][4], bhf[2][4], blf[2][4];
#pragma unroll
            for (int mt = 0; mt < 2; mt++) {
                uint32_t bo = (uint32_t)((wm + mt * 16 + (lane & 15)) * 128
                                         + ks * 32 + (lane >> 4) * 16);
                uint32_t sw = SWZ128(bo);
                ldsm_x4(sbase + OFF_AH + sw, ahf[mt]);
                ldsm_x4(sbase + OFF_AL + sw, alf[mt]);
            }
#pragma unroll
            for (int np = 0; np < 2; np++) {
                uint32_t bo = (uint32_t)((wn + np * 16 + (lane & 7) + ((lane >> 4) & 1) * 8) * 128
                                         + ks * 32 + ((lane >> 3) & 1) * 16);
                uint32_t sw = SWZ128(bo);
                ldsm_x4(sbase + OFF_BH + sw, bhf[np]);
                ldsm_x4(sbase + OFF_BL + sw, blf[np]);
            }
            // combo-outer: 8 independent mma between same-acc reuse
#pragma unroll
            for (int combo = 0; combo < 3; combo++)
#pragma unroll
                for (int mt = 0; mt < 2; mt++)
#pragma unroll
                    for (int nt = 0; nt < 4; nt++) {
                        const uint32_t* ap = (combo == 2) ? alf[mt] : ahf[mt];
                        const uint32_t* bp = (combo == 1) ? &blf[nt >> 1][(nt & 1) * 2]
                                                          : &bhf[nt >> 1][(nt & 1) * 2];
                        mma_bf16(acc[mt][nt], ap, bp);
                    }
        }
        __syncthreads();
        if (c + 1 < NCH) {
            a_store(buf ^ 1);
            if (c + 2 < NCH) { a_load(c + 2); b_issue(c + 2, buf); CP_COMMIT(); CP_WAIT1(); }
            else             { CP_WAIT0(); }
            __syncthreads();
        }
    }

    // ---- epilogue: relu + bf16 hi/lo split out ----
#pragma unroll
    for (int mt = 0; mt < 2; mt++) {
        int r0 = brow + wm + mt * 16 + (lane >> 2);
#pragma unroll
        for (int nt = 0; nt < 4; nt++) {
            int cc = bcol + wn + nt * 8 + (lane & 3) * 2;
            float b0 = bias[cc], b1 = bias[cc + 1];
#pragma unroll
            for (int half = 0; half < 2; half++) {
                int r = r0 + half * 8;
                if (r < M) {
                    float vx = fmaxf(acc[mt][nt][half * 2 + 0] + b0, 0.f);
                    float vy = fmaxf(acc[mt][nt][half * 2 + 1] + b1, 0.f);
                    uint32_t hi, lo;
                    split_pair(vx, vy, hi, lo);
                    *(uint32_t*)(O1h + (size_t)r * NH + cc) = hi;
                    *(uint32_t*)(O1l + (size_t)r * NH + cc) = lo;
                }
            }
        }
    }
}

// ================= GEMM2: hA(fp16) = h1 @ W2 + b2 ; hid = temp[0]*hA =================
__global__ __launch_bounds__(256, 2) void k_gemm2(
    const __nv_bfloat16* __restrict__ Ah, const __nv_bfloat16* __restrict__ Al,
    const __nv_bfloat16* __restrict__ BTh, const __nv_bfloat16* __restrict__ BTl,
    const float* __restrict__ bias, __half* __restrict__ O1, float* __restrict__ O2,
    const float* __restrict__ temp, int M)
{
    constexpr int KT = NH, NT = 64, WN = 32;
    constexpr int NCH = KT / 64;                     // 4
    constexpr int OFF_AH = 0, OFF_AL = 16384, OFF_BH = 32768, OFF_BL = 32768 + NT * 128;
    constexpr int STG = 2 * 16384 + 2 * NT * 128;    // 48KB / stage

    extern __shared__ char smem_raw[];
    uint32_t sb0 = smem_u32(smem_raw);
    uint32_t pad = (1024u - (sb0 & 1023u)) & 1023u;
    uint32_t sb = sb0 + pad;

    int tid = threadIdx.x, wid = tid >> 5, lane = tid & 31;
    int brow = blockIdx.x * 128;
    int wm = (wid & 3) * 32, wn = (wid >> 2) * WN;

    int am = tid >> 1, asub = tid & 1;
    int bn = tid & (NT - 1), bsub = tid >> 6;

    auto issue = [&](int c, int buf) {
        uint32_t base = sb + buf * STG;
        const __nv_bfloat16* pah = Ah + (size_t)(brow + am) * KT + c * 64;
        const __nv_bfloat16* pal = Al + (size_t)(brow + am) * KT + c * 64;
#pragma unroll
        for (int i = 0; i < 4; i++) {
            int g = asub * 4 + i;
            uint32_t sw = SWZ128((uint32_t)(am * 128 + g * 16));
            cp16(base + OFF_AH + sw, pah + g * 8);
            cp16(base + OFF_AL + sw, pal + g * 8);
        }
        const __nv_bfloat16* pbh = BTh + (size_t)bn * KT + c * 64;
        const __nv_bfloat16* pbl = BTl + (size_t)bn * KT + c * 64;
#pragma unroll
        for (int i = 0; i < 2; i++) {
            int g = bsub * 2 + i;
            uint32_t sw = SWZ128((uint32_t)(bn * 128 + g * 16));
            cp16(base + OFF_BH + sw, pbh + g * 8);
            cp16(base + OFF_BL + sw, pbl + g * 8);
        }
    };

    float acc[2][4][4];
#pragma unroll
    for (int mt = 0; mt < 2; mt++)
#pragma unroll
        for (int nt = 0; nt < 4; nt++)
#pragma unroll
            for (int j = 0; j < 4; j++) acc[mt][nt][j] = 0.0f;

    issue(0, 0); CP_COMMIT();
    issue(1, 1); CP_COMMIT();
    CP_WAIT1();
    __syncthreads();

    for (int c = 0; c < NCH; c++) {
        int buf = c & 1;
        uint32_t sbase = sb + buf * STG;
#pragma unroll
        for (int ks = 0; ks < 4; ks++) {
            uint32_t ahf[2][4], alf[2][4], bhf[2][4], blf[2][4];
#pragma unroll
            for (int mt = 0; mt < 2; mt++) {
                uint32_t bo = (uint32_t)((wm + mt * 16 + (lane & 15)) * 128
                                         + ks * 32 + (lane >> 4) * 16);
                uint32_t sw = SWZ128(bo);
                ldsm_x4(sbase + OFF_AH + sw, ahf[mt]);
                ldsm_x4(sbase + OFF_AL + sw, alf[mt]);
            }
#pragma unroll
            for (int np = 0; np < 2; np++) {
                uint32_t bo = (uint32_t)((wn + np * 16 + (lane & 7) + ((lane >> 4) & 1) * 8) * 128
                                         + ks * 32 + ((lane >> 3) & 1) * 16);
                uint32_t sw = SWZ128(bo);
                ldsm_x4(sbase + OFF_BH + sw, bhf[np]);
                ldsm_x4(sbase + OFF_BL + sw, blf[np]);
            }
#pragma unroll
            for (int combo = 0; combo < 3; combo++)
#pragma unroll
                for (int mt = 0; mt < 2; mt++)
#pragma unroll
                    for (int nt = 0; nt < 4; nt++) {
                        const uint32_t* ap = (combo == 2) ? alf[mt] : ahf[mt];
                        const uint32_t* bp = (combo == 1) ? &blf[nt >> 1][(nt & 1) * 2]
                                                          : &bhf[nt >> 1][(nt & 1) * 2];
                        mma_bf16(acc[mt][nt], ap, bp);
                    }
        }
        __syncthreads();
        if (c + 2 < NCH) { issue(c + 2, buf); CP_COMMIT(); CP_WAIT1(); __syncthreads(); }
        else if (c + 1 < NCH) { CP_WAIT0(); __syncthreads(); }
    }

    float t0 = __ldg(temp);
#pragma unroll
    for (int mt = 0; mt < 2; mt++) {
        int r0 = brow + wm + mt * 16 + (lane >> 2);
#pragma unroll
        for (int nt = 0; nt < 4; nt++) {
            int cc = wn + nt * 8 + (lane & 3) * 2;
            float b0 = bias[cc], b1 = bias[cc + 1];
#pragma unroll
            for (int half = 0; half < 2; half++) {
                int r = r0 + half * 8;
                if (r < M) {
                    float vx = acc[mt][nt][half * 2 + 0] + b0;
                    float vy = acc[mt][nt][half * 2 + 1] + b1;
                    *(__half2*)(O1 + (size_t)r * NCLS + cc) = __floats2half2_rn(vx, vy);
                    float2 s; s.x = t0 * vx; s.y = t0 * vy;
                    *(float2*)(O2 + (size_t)r * NCLS + cc) = s;
                }
            }
        }
    }
}

// ---------------- CSR build ----------------
__global__ void k_zero_cnt(int* cnt, int n) {
    int i = blockIdx.x * blockDim.x + threadIdx.x;
    if (i < n) cnt[i] = 0;
}
__global__ void k_hist(const int* __restrict__ colp, int* cnt, int E) {
    int e = blockIdx.x * blockDim.x + threadIdx.x;
    if (e < E) atomicAdd(&cnt[colp[e]], 1);
}
__global__ __launch_bounds__(SCAN_B) void k_scan_block(
    const int* __restrict__ cnt, int* __restrict__ off, int* __restrict__ bsum, int n)
{
    __shared__ int s[SCAN_B];
    int i = blockIdx.x * SCAN_B + threadIdx.x;
    int v = (i < n) ? cnt[i] : 0;
    s[threadIdx.x] = v;
    __syncthreads();
#pragma unroll
    for (int d = 1; d < SCAN_B; d <<= 1) {
        int t = (threadIdx.x >= d) ? s[threadIdx.x - d] : 0;
        __syncthreads();
        s[threadIdx.x] += t;
        __syncthreads();
    }
    if (i < n) off[i] = s[threadIdx.x] - v;
    if (threadIdx.x == SCAN_B - 1) bsum[blockIdx.x] = s[SCAN_B - 1];
}
__global__ void k_scan_bsum(int* bsum, int nb, int* off, int n, int E) {
    int acc = 0;
    for (int i = 0; i < nb; i++) { int v = bsum[i]; bsum[i] = acc; acc += v; }
    off[n] = E;
}
__global__ __launch_bounds__(SCAN_B) void k_add_off(
    int* off, const int* __restrict__ bsum, int* cur, int n)
{
    int i = blockIdx.x * SCAN_B + threadIdx.x;
    if (i < n) {
        int v = off[i] + bsum[blockIdx.x];
        off[i] = v;
        cur[i] = v;
    }
}
__global__ void k_node_norm(const int* __restrict__ cnt, float* dis, float* selfw, int n) {
    int i = blockIdx.x * blockDim.x + threadIdx.x;
    if (i < n) {
        float d = (float)(cnt[i] + 1);
        dis[i]   = rsqrtf(d);
        selfw[i] = 1.0f / d;
    }
}
__global__ void k_scatter(const int* __restrict__ row, const int* __restrict__ colp,
                          const float* __restrict__ dis, int* cur,
                          int2* __restrict__ sw, int E) {
    int e = blockIdx.x * blockDim.x + threadIdx.x;
    if (e < E) {
        int r = row[e], c = colp[e];
        int pos = atomicAdd(&cur[c], 1);
        sw[pos] = make_int2(r, __float_as_int(dis[r] * dis[c]));
    }
}

// ---------------- fused CSR propagation (fp16 state, fp32 accum, packed edges) ----------------
// last hop: fuse hid accumulation + log_softmax, write output directly.
__global__ __launch_bounds__(256) void k_prop(
    const int* __restrict__ offp, const int2* __restrict__ sw,
    const float* __restrict__ selfw, const __half2* __restrict__ hc, __half2* __restrict__ hn,
    float2* __restrict__ hid, const float* __restrict__ temp, int kidx, int last,
    float2* __restrict__ outp, int N)
{
    int gw = (blockIdx.x * blockDim.x + threadIdx.x) >> 5;
    if (gw >= N) return;
    int lane = threadIdx.x & 31;

    int s = offp[gw];
    int e = offp[gw + 1];
    float accx = 0.0f, accy = 0.0f;

    for (int base = s; base < e; base += 32) {
        int m = e - base; if (m > 32) m = 32;
        int idx = 0; float wv = 0.0f;
        if (lane < m) {
            int2 p = sw[base + lane];
            idx = p.x;
            wv  = __int_as_float(p.y);
        }
#pragma unroll 4
        for (int t = 0; t < m; t++) {
            int   ib = __shfl_sync(0xFFFFFFFFu, idx, t);
            float wb = __shfl_sync(0xFFFFFFFFu, wv,  t);
            float2 v = __half22float2(hc[(size_t)ib * 32 + lane]);
            accx += wb * v.x;
            accy += wb * v.y;
        }
    }
    float swv = selfw[gw];
    float2 hv = __half22float2(hc[(size_t)gw * 32 + lane]);
    accx += swv * hv.x;
    accy += swv * hv.y;

    size_t o = (size_t)gw * 32 + lane;
    float tc = temp[kidx];
    float2 hd = hid[o];
    hd.x += tc * accx;
    hd.y += tc * accy;

    if (!last) {
        hn[o] = __floats2half2_rn(accx, accy);
        hid[o] = hd;
    } else {
        // fused log_softmax over the 64-class row held by this warp
        float m = fmaxf(hd.x, hd.y);
#pragma unroll
        for (int d = 16; d > 0; d >>= 1)
            m = fmaxf(m, __shfl_xor_sync(0xFFFFFFFFu, m, d));
        float sum = __expf(hd.x - m) + __expf(hd.y - m);
#pragma unroll
        for (int d = 16; d > 0; d >>= 1)
            sum += __shfl_xor_sync(0xFFFFFFFFu, sum, d);
        float lse = m + __logf(sum);
        float2 r; r.x = hd.x - lse; r.y = hd.y - lse;
        outp[o] = r;
    }
}

// ---------------- launch ----------------
extern "C" void kernel_launch(void* const* d_in, const int* in_sizes, int n_in,
                              void* d_out, int out_size) {
    const float* x    = (const float*)d_in[0];
    const int*   ei   = (const int*)d_in[1];
    const float* W1   = (const float*)d_in[2];
    const float* b1   = (const float*)d_in[3];
    const float* W2   = (const float*)d_in[4];
    const float* b2   = (const float*)d_in[5];
    const float* temp = (const float*)d_in[6];

    int N = in_sizes[0] / NF;
    int E = in_sizes[1] / 2;
    const int* row  = ei;
    const int* colp = ei + E;

    int *cnt, *off, *cur, *bsum;
    int2 *sw;
    float *dis, *selfw, *hid;
    __half *hA, *hB;
    __nv_bfloat16 *w1th, *w1tl, *w2th, *w2tl, *h1h, *h1l;
    cudaGetSymbolAddress((void**)&cnt,   g_cnt);
    cudaGetSymbolAddress((void**)&off,   g_off);
    cudaGetSymbolAddress((void**)&cur,   g_cur);
    cudaGetSymbolAddress((void**)&bsum,  g_bsum);
    cudaGetSymbolAddress((void**)&sw,    g_sw);
    cudaGetSymbolAddress((void**)&dis,   g_dis);
    cudaGetSymbolAddress((void**)&selfw, g_selfw);
    cudaGetSymbolAddress((void**)&w1th,  g_w1th);
    cudaGetSymbolAddress((void**)&w1tl,  g_w1tl);
    cudaGetSymbolAddress((void**)&w2th,  g_w2th);
    cudaGetSymbolAddress((void**)&w2tl,  g_w2tl);
    cudaGetSymbolAddress((void**)&h1h,   g_h1h);
    cudaGetSymbolAddress((void**)&h1l,   g_h1l);
    cudaGetSymbolAddress((void**)&hA,    g_hA);
    cudaGetSymbolAddress((void**)&hB,    g_hB);
    cudaGetSymbolAddress((void**)&hid,   g_hid);

    // one-time side stream + fork/join events (capture-safe parallel branch)
    static cudaStream_t s1 = nullptr;
    static cudaEvent_t evA = nullptr, evB = nullptr;
    if (s1 == nullptr) {
        cudaStreamCreateWithFlags(&s1, cudaStreamNonBlocking);
        cudaEventCreateWithFlags(&evA, cudaEventDisableTiming);
        cudaEventCreateWithFlags(&evB, cudaEventDisableTiming);
    }

    const int T = 256;
    int nblk = (N + 127) / 128;                               // 782
    const int SM1 = 2 * 65536 + 1024;                         // 132096 (1 CTA/SM, 512 thr)
    const int SM2 = 2 * (2 * 16384 + 2 * 64 * 128) + 1024;    //  99328
    cudaFuncSetAttribute(k_gemm1, cudaFuncAttributeMaxDynamicSharedMemorySize, SM1);
    cudaFuncSetAttribute(k_gemm2, cudaFuncAttributeMaxDynamicSharedMemorySize, SM2);

    // main stream: weights split + GEMMs.  side stream s1: CSR build (independent).
    k_split_w  <<<(NF * NH + T - 1) / T, T>>>(W1, w1th, w1tl, NF, NH);     // 1 (s0)
    k_split_w  <<<(NH * NCLS + T - 1) / T, T>>>(W2, w2th, w2tl, NH, NCLS); // 2 (s0)
    cudaEventRecord(evA, 0);
    cudaStreamWaitEvent(s1, evA, 0);
    k_zero_cnt <<<(N + T - 1) / T, T, 0, s1>>>(cnt, N);                     // 3 (s1)
    dim3 g1(NH / 128, nblk);                              // x = N-tiles (A sharers adjacent)
    k_gemm1    <<<g1, 512, SM1>>>(x, w1th, w1tl, b1, h1h, h1l, N);          // 4 (s0) <- profiled
    k_hist     <<<(E + T - 1) / T, T, 0, s1>>>(colp, cnt, E);               // (s1)
    k_scan_block<<<NBLK_SCAN, SCAN_B, 0, s1>>>(cnt, off, bsum, N);
    k_scan_bsum<<<1, 1, 0, s1>>>(bsum, NBLK_SCAN, off, N, E);
    k_add_off  <<<NBLK_SCAN, SCAN_B, 0, s1>>>(off, bsum, cur, N);
    k_node_norm<<<(N + T - 1) / T, T, 0, s1>>>(cnt, dis, selfw, N);
    k_scatter  <<<(E + T - 1) / T, T, 0, s1>>>(row, colp, dis, cur, sw, E);
    cudaEventRecord(evB, s1);
    k_gemm2    <<<nblk, 256, SM2>>>(h1h, h1l, w2th, w2tl, b2, hA, hid, temp, N);
    cudaStreamWaitEvent(0, evB, 0);    // join before propagation

    __half* curh = hA;
    __half* nxth = hB;
    int pblocks = (int)(((long long)N * 32 + T - 1) / T);
    for (int k = 0; k < KHOP; k++) {
        int last = (k == KHOP - 1) ? 1 : 0;
        k_prop<<<pblocks, T>>>(off, sw, selfw,
                               (const __half2*)curh, (__half2*)nxth,
                               (float2*)hid, temp, k + 1, last, (float2*)d_out, N);
        __half* t2 = curh; curh = nxth; nxth = t2;
    }
}